// round 7
// baseline (speedup 1.0000x reference)
#include <cuda_runtime.h>
#include <cstdint>
#include <cstddef>

// Problem dims
#define TT 700
#define BB 64
#define UU 400
#define GG 1600   // 4*U
#define FF 3
#define NCTA 148
#define NCOL 12   // 3 units * 4 gates per CTA (U padded to 148*3=444)

typedef unsigned long long ull;

// ---------------- static device scratch -------------------------------------
__device__ float g_xp [(size_t)TT * GG * BB];   // [t][col][b]
__device__ float g_hs0[(size_t)TT * UU * BB];   // [t][u][b]
__device__ float g_hs1[(size_t)TT * UU * BB];   // [t][u][b]
__device__ unsigned g_flags[NCTA];              // per-CTA own-arrival count (self-read only)
__device__ unsigned g_ctr;                      // global arrival counter (red.add target)

// ---------------- helpers ----------------------------------------------------
__device__ __forceinline__ unsigned ld_acq(const unsigned* p) {
    unsigned v;
    asm volatile("ld.acquire.gpu.u32 %0, [%1];" : "=r"(v) : "l"(p) : "memory");
    return v;
}
__device__ __forceinline__ void red_rel_add(unsigned* p, unsigned v) {
    asm volatile("red.release.gpu.global.add.u32 [%0], %1;" :: "l"(p), "r"(v) : "memory");
}
// packed fp32x2 FMA (Blackwell): d = a*b + d on two fp32 lanes of a 64-bit pair
__device__ __forceinline__ void ffma2(ull& d, ull a, ull b) {
    asm("fma.rn.f32x2 %0, %1, %2, %0;" : "+l"(d) : "l"(a), "l"(b));
}
__device__ __forceinline__ ull dup2(float w) {
    ull r; asm("mov.b64 %0, {%1, %1};" : "=l"(r) : "f"(w)); return r;
}
__device__ __forceinline__ float f2lo(ull v){ return __int_as_float((int)(unsigned)v); }
__device__ __forceinline__ float f2hi(ull v){ return __int_as_float((int)(v >> 32)); }
__device__ __forceinline__ float sigm(float x) { return 1.0f / (1.0f + __expf(-x)); }

// ---------------- layer-0 input projection (K = F = 3) -----------------------
__global__ void xp_l0_kernel(const float* __restrict__ x,
                             const float* __restrict__ Wx0,
                             const float* __restrict__ b0)
{
    int t = blockIdx.x;
    __shared__ float xs[BB * FF];
    __shared__ float ws[FF * GG];
    __shared__ float bs[GG];
    int tid = threadIdx.x;
    if (tid < BB * FF) {
        int b = tid / FF, d = tid % FF;
        xs[tid] = x[(size_t)b * (TT * FF) + t * FF + d];
    }
    for (int i = tid; i < FF * GG; i += 256) ws[i] = Wx0[i];
    for (int i = tid; i < GG; i += 256) bs[i] = b0[i];
    __syncthreads();
    float* dst = g_xp + (size_t)t * GG * BB;
    for (int idx = tid; idx < GG * BB; idx += 256) {
        int col = idx >> 6, b = idx & 63;
        float v = bs[col]
                + xs[b * 3 + 0] * ws[col]
                + xs[b * 3 + 1] * ws[GG + col]
                + xs[b * 3 + 2] * ws[2 * GG + col];
        dst[idx] = v;
    }
}

// ---------------- xp GEMM layers 1,2 (K=400): f32x2, pre-dup'd W, dbl buffer -
// g_xp[t][col][b] = bias[col] + sum_u hs[t][u][b] * Wx[u][col]
// grid (25, 700), block 256; CTA tile 64 cols x 64 b; k-chunks of 16.
// Inner iter per thread: 1 LDS.128 (a pair) + 2 LDS.128 (4 pre-dup'd w) + 8 FFMA2.
__global__ void __launch_bounds__(256) xp_gemm_kernel(int srcsel,
                                                      const float* __restrict__ Wx,
                                                      const float* __restrict__ bias)
{
    const float* hs = srcsel ? g_hs1 : g_hs0;
    int t  = blockIdx.y;
    int c0 = blockIdx.x * 64;

    __shared__ float4 As[2][256];       // [buf][k16][b64/4]   8 KB
    __shared__ ull    Ws2[2][16 * 64];  // [buf][k16][c64] dup pairs  16 KB

    int tid = threadIdx.x;
    int tc = tid & 15;   // col group (4 cols)
    int tb = tid >> 4;   // b group (4 b)
    int r  = tid >> 4;   // load row in chunk
    int q  = tid & 15;   // load float4 idx

    const float* hsrc = hs + (size_t)t * UU * BB;

    // prologue: chunk 0
    float4 pa = ((const float4*)(hsrc + (size_t)r * BB))[q];
    float4 pw = ((const float4*)(Wx + (size_t)r * GG + c0))[q];
    As[0][tid] = pa;
    {
        ulonglong2 d0, d1;
        d0.x = dup2(pw.x); d0.y = dup2(pw.y);
        d1.x = dup2(pw.z); d1.y = dup2(pw.w);
        *(ulonglong2*)&Ws2[0][r * 64 + q * 4]     = d0;
        *(ulonglong2*)&Ws2[0][r * 64 + q * 4 + 2] = d1;
    }
    __syncthreads();

    ull acc[4][2];
#pragma unroll
    for (int c = 0; c < 4; c++) { acc[c][0] = 0ull; acc[c][1] = 0ull; }

    for (int kc = 0; kc < 25; kc++) {
        int buf = kc & 1;
        if (kc < 24) {
            int row = (kc + 1) * 16 + r;
            pa = ((const float4*)(hsrc + (size_t)row * BB))[q];
            pw = ((const float4*)(Wx + (size_t)row * GG + c0))[q];
        }
#pragma unroll
        for (int k = 0; k < 16; k++) {
            ulonglong2 a = *(const ulonglong2*)&As[buf][k * 16 + tb];
            const ull* wrow = &Ws2[buf][k * 64 + tc * 4];
            ulonglong2 w01 = *(const ulonglong2*)wrow;
            ulonglong2 w23 = *(const ulonglong2*)(wrow + 2);
            ffma2(acc[0][0], a.x, w01.x); ffma2(acc[0][1], a.y, w01.x);
            ffma2(acc[1][0], a.x, w01.y); ffma2(acc[1][1], a.y, w01.y);
            ffma2(acc[2][0], a.x, w23.x); ffma2(acc[2][1], a.y, w23.x);
            ffma2(acc[3][0], a.x, w23.y); ffma2(acc[3][1], a.y, w23.y);
        }
        if (kc < 24) {
            As[buf ^ 1][tid] = pa;
            ulonglong2 d0, d1;
            d0.x = dup2(pw.x); d0.y = dup2(pw.y);
            d1.x = dup2(pw.z); d1.y = dup2(pw.w);
            *(ulonglong2*)&Ws2[buf ^ 1][r * 64 + q * 4]     = d0;
            *(ulonglong2*)&Ws2[buf ^ 1][r * 64 + q * 4 + 2] = d1;
            __syncthreads();
        }
    }

#pragma unroll
    for (int c = 0; c < 4; c++) {
        int col = c0 + tc * 4 + c;
        float bv = bias[col];
        float4 o;
        o.x = f2lo(acc[c][0]) + bv; o.y = f2hi(acc[c][0]) + bv;
        o.z = f2lo(acc[c][1]) + bv; o.w = f2hi(acc[c][1]) + bv;
        ((float4*)(g_xp + (size_t)(t * GG + col) * BB))[tb] = o;
    }
}

// ---------------- persistent per-layer LSTM scan -----------------------------
// 148 CTAs x 256 threads (1/SM). CTA owns units u0..u0+2 (padded to 444).
// warp = k-slice (8 x 50 rows); colg=(tid>>3)&3 (3 cols), rowg=tid&7 (8 b).
// Warp-local refill (warp only reads the h rows it writes).
// Grid barrier: arrive = red.release.add on ONE counter; target uses the CTA's
// OWN arrival count (g_flags[cta], self-written only) so launch skew between
// CTAs cannot skew targets. Wrap-safe signed compare.
#define SCAN_SMEM 178944

template<int N>
__device__ __forceinline__ void compute_rows(const float* h_sm, const ull* w2s,
                                             int k0, int rowg, int colg,
                                             ull (&acc)[3][4])
{
    const char* hp = (const char*)(h_sm + (size_t)k0 * BB + rowg * 8);
    const ull*  wp = w2s + (size_t)k0 * 16 + colg * 4;
#pragma unroll 10
    for (int it = 0; it < N; it++) {
        ulonglong2 hA = *(const ulonglong2*)hp;         // b0..b3
        ulonglong2 hB = *(const ulonglong2*)(hp + 16);  // b4..b7
        ulonglong2 wAB = *(const ulonglong2*)wp;        // cols 0,1 (pre-dup'd)
        ull wC = wp[2];                                 // col 2
        ffma2(acc[0][0], hA.x, wAB.x); ffma2(acc[0][1], hA.y, wAB.x);
        ffma2(acc[0][2], hB.x, wAB.x); ffma2(acc[0][3], hB.y, wAB.x);
        ffma2(acc[1][0], hA.x, wAB.y); ffma2(acc[1][1], hA.y, wAB.y);
        ffma2(acc[1][2], hB.x, wAB.y); ffma2(acc[1][3], hB.y, wAB.y);
        ffma2(acc[2][0], hA.x, wC);    ffma2(acc[2][1], hA.y, wC);
        ffma2(acc[2][2], hB.x, wC);    ffma2(acc[2][3], hB.y, wC);
        hp += BB * 4;
        wp += 16;
    }
}

__global__ void __launch_bounds__(256, 1) scan_kernel(const float* __restrict__ Wh_l,
                                                      const float* __restrict__ pi_l,
                                                      const float* __restrict__ pf_l,
                                                      const float* __restrict__ po_l,
                                                      int outsel)
{
    float* hs_out = outsel ? g_hs1 : g_hs0;

    extern __shared__ char smraw[];
    float* h_sm = (float*)smraw;                 // [400][64]
    ull*   w2s  = (ull*)(smraw + 102400);        // [400][16] duplicated pairs
    float* red  = (float*)(smraw + 153600);      // [8][12][64]
    float* c_sm = (float*)(smraw + 178176);      // [3][64]

    const int tid  = threadIdx.x;
    const int cta  = blockIdx.x;
    const int u0   = cta * 3;
    const int ks   = tid >> 5;          // warp id = k slice
    const int lane = tid & 31;
    const int colg = (tid >> 3) & 3;
    const int rowg = tid & 7;

    // init h_sm zero (t=0 state)
    for (int i = tid; i < UU * BB / 4; i += 256)
        ((float4*)h_sm)[i] = make_float4(0.f, 0.f, 0.f, 0.f);
    // init duplicated weights: slot s = cg*4 + j (j<3 used, j==3 pad)
    for (int i = tid; i < UU * 16; i += 256) {
        int k = i >> 4, s = i & 15;
        int cg = s >> 2, j = s & 3;
        float v = 0.f;
        if (j < 3) {
            int lc = cg * 3 + j;
            int u  = u0 + (lc >> 2);
            int g  = lc & 3;
            if (u < UU) v = Wh_l[(size_t)k * GG + g * UU + u];
        }
        w2s[i] = dup2(v);
    }
    if (tid < 3 * BB) c_sm[tid] = 0.f;

    // gate-thread constants
    float piv = 0.f, pfv = 0.f, pov = 0.f;
    int gu = 0, gb = 0, gj = 0;
    const bool gthr = (tid < 3 * BB);
    bool gvalid = false;
    if (gthr) {
        gj = tid >> 6; gb = tid & 63; gu = u0 + gj;
        gvalid = (gu < UU);
        if (gvalid) { piv = pi_l[gu]; pfv = pf_l[gu]; pov = po_l[gu]; }
    }

    // own arrival count (only this CTA ever writes g_flags[cta]) — launch-skew safe
    const unsigned Abase = g_flags[cta];
    __syncthreads();

    const int kbase = ks * 50;
    float4* dst4 = (float4*)(h_sm + kbase * BB);           // this warp's 50 rows
    float* rp = red + (ks * NCOL + colg * 3) * BB + rowg * 8;

    for (int t = 0; t < TT; t++) {
        // prefetch xp for the gate phase (overlaps with compute)
        float xp0 = 0.f, xp1 = 0.f, xp2 = 0.f, xp3 = 0.f;
        if (gvalid) {
            const float* xpp = g_xp + ((size_t)t * GG + gu) * BB + gb;
            xp0 = __ldg(xpp);
            xp1 = __ldg(xpp + (size_t)UU * BB);
            xp2 = __ldg(xpp + (size_t)2 * UU * BB);
            xp3 = __ldg(xpp + (size_t)3 * UU * BB);
        }

        if (t > 0) {
            // warp-local refill of own 50 h-rows: one batched LDG->STS burst
            const float4* src4 = (const float4*)(hs_out + ((size_t)(t - 1) * UU + kbase) * BB);
            float4 tmp[25];
#pragma unroll
            for (int i = 0; i < 25; i++) tmp[i] = src4[i * 32 + lane];
#pragma unroll
            for (int i = 0; i < 25; i++) dst4[i * 32 + lane] = tmp[i];
            __syncwarp();
        }

        ull acc[3][4];
#pragma unroll
        for (int c = 0; c < 3; c++)
#pragma unroll
            for (int p = 0; p < 4; p++) acc[c][p] = 0ull;

        compute_rows<50>(h_sm, w2s, kbase, rowg, colg, acc);

        // write partial sums
#pragma unroll
        for (int c = 0; c < 3; c++) {
            ulonglong2 s0; s0.x = acc[c][0]; s0.y = acc[c][1];
            ulonglong2 s1; s1.x = acc[c][2]; s1.y = acc[c][3];
            *(ulonglong2*)(rp + (size_t)c * BB)     = s0;
            *(ulonglong2*)(rp + (size_t)c * BB + 4) = s1;
        }
        __syncthreads();

        // gate phase: 192 threads, one per (unit j, batch b)
        if (gthr) {
            float s0 = 0.f, s1 = 0.f, s2 = 0.f, s3 = 0.f;
#pragma unroll
            for (int q = 0; q < 8; q++) {
                const float* r2 = red + (q * NCOL + gj * 4) * BB + gb;
                s0 += r2[0]; s1 += r2[BB]; s2 += r2[2 * BB]; s3 += r2[3 * BB];
            }
            if (gvalid) {
                float z0 = xp0 + s0, z1 = xp1 + s1, z2 = xp2 + s2, z3 = xp3 + s3;
                float cold = c_sm[tid];
                float iv = sigm(z0 + piv * cold);
                float fv = sigm(z1 + pfv * cold);
                float cn = fv * cold + iv * tanhf(z2);
                float ov = sigm(z3 + pov * cn);
                float hv = ov * tanhf(cn);
                c_sm[tid] = cn;
                hs_out[((size_t)t * UU + gu) * BB + gb] = hv;
            }
        }
        __syncthreads();   // orders gate STGs before tid0's release-arrive,
                           // and protects red/h_sm reuse next iteration

        if (t < TT - 1) {
            // arrive: one release-RMW on the shared counter; release sequence of
            // all 148 RMWs synchronizes-with the reader's acquire load below.
            unsigned tgt = (unsigned)NCTA * (Abase + (unsigned)t + 1u);
            if (tid == 0) {
                red_rel_add(&g_ctr, 1u);
                // poll single line until all arrived (wrap-safe signed compare)
                while ((int)(ld_acq(&g_ctr) - tgt) < 0) __nanosleep(16);
            }
            __syncthreads();   // release all warps into their private refill
        }
    }

    // persist own arrival count for the next launch (self-read only)
    if (tid == 0) g_flags[cta] = Abase + (unsigned)(TT - 1);
}

// ---------------- final projection ------------------------------------------
__global__ void final_kernel(const float* __restrict__ Wd,
                             const float* __restrict__ bd,
                             float* __restrict__ out)
{
    int t = blockIdx.x;
    int tid = threadIdx.x;  // 192
    __shared__ float wds[UU * FF];
    for (int i = tid; i < UU * FF; i += 192) wds[i] = Wd[i];
    __syncthreads();
    int b = tid / FF, f = tid % FF;
    const float* h = g_hs0 + (size_t)t * UU * BB;
    float acc = bd[f];
#pragma unroll 4
    for (int u = 0; u < UU; u++)
        acc += h[(size_t)u * BB + b] * wds[u * FF + f];
    out[(size_t)b * (TT * FF) + t * FF + f] = acc;
}

// ---------------- launch -----------------------------------------------------
extern "C" void kernel_launch(void* const* d_in, const int* in_sizes, int n_in,
                              void* d_out, int out_size)
{
    (void)in_sizes; (void)n_in; (void)out_size;
    const float* x   = (const float*)d_in[0];
    const float* Wx0 = (const float*)d_in[1];
    const float* Wx1 = (const float*)d_in[2];
    const float* Wx2 = (const float*)d_in[3];
    const float* Wh  = (const float*)d_in[4];
    const float* bb  = (const float*)d_in[5];
    const float* pi  = (const float*)d_in[6];
    const float* pf  = (const float*)d_in[7];
    const float* po  = (const float*)d_in[8];
    const float* Wd  = (const float*)d_in[9];
    const float* bd  = (const float*)d_in[10];
    float* out = (float*)d_out;

    cudaFuncSetAttribute(scan_kernel, cudaFuncAttributeMaxDynamicSharedMemorySize, SCAN_SMEM);

    // layer 0
    xp_l0_kernel<<<TT, 256>>>(x, Wx0, bb);
    scan_kernel<<<NCTA, 256, SCAN_SMEM>>>(Wh, pi, pf, po, /*outsel=*/0);
    // layer 1
    xp_gemm_kernel<<<dim3(GG / 64, TT), 256>>>(/*src=*/0, Wx1, bb + GG);
    scan_kernel<<<NCTA, 256, SCAN_SMEM>>>(Wh + (size_t)UU * GG, pi + UU, pf + UU, po + UU, 1);
    // layer 2
    xp_gemm_kernel<<<dim3(GG / 64, TT), 256>>>(/*src=*/1, Wx2, bb + 2 * GG);
    scan_kernel<<<NCTA, 256, SCAN_SMEM>>>(Wh + (size_t)2 * UU * GG, pi + 2 * UU, pf + 2 * UU, po + 2 * UU, 0);
    // output projection
    final_kernel<<<TT, 192>>>(Wd, bd, out);
}

// round 8
// speedup vs baseline: 1.0664x; 1.0664x over previous
#include <cuda_runtime.h>
#include <cstdint>
#include <cstddef>

// Problem dims
#define TT 700
#define BB 64
#define UU 400
#define GG 1600   // 4*U
#define FF 3
#define NCTA 148
#define NCOL 12   // 3 units * 4 gates per CTA (U padded to 148*3=444)

typedef unsigned long long ull;

// ---------------- static device scratch -------------------------------------
__device__ float g_xp [(size_t)TT * GG * BB];   // [t][col][b]
__device__ float g_hs0[(size_t)TT * UU * BB];   // [t][u][b]
__device__ float g_hs1[(size_t)TT * UU * BB];   // [t][u][b]
__device__ unsigned g_flags[NCTA];              // zero-init, monotonic barrier counters

// ---------------- helpers ----------------------------------------------------
__device__ __forceinline__ unsigned ld_acq(const unsigned* p) {
    unsigned v;
    asm volatile("ld.acquire.gpu.u32 %0, [%1];" : "=r"(v) : "l"(p) : "memory");
    return v;
}
__device__ __forceinline__ void st_rel(unsigned* p, unsigned v) {
    asm volatile("st.release.gpu.u32 [%0], %1;" :: "l"(p), "r"(v) : "memory");
}
// packed fp32x2 FMA (Blackwell): d = a*b + d on two fp32 lanes of a 64-bit pair
__device__ __forceinline__ void ffma2(ull& d, ull a, ull b) {
    asm("fma.rn.f32x2 %0, %1, %2, %0;" : "+l"(d) : "l"(a), "l"(b));
}
__device__ __forceinline__ ull dup2(float w) {
    ull r; asm("mov.b64 %0, {%1, %1};" : "=l"(r) : "f"(w)); return r;
}
__device__ __forceinline__ float f2lo(ull v){ return __int_as_float((int)(unsigned)v); }
__device__ __forceinline__ float f2hi(ull v){ return __int_as_float((int)(v >> 32)); }
__device__ __forceinline__ float sigm(float x) { return 1.0f / (1.0f + __expf(-x)); }

// ---------------- layer-0 input projection (K = F = 3) -----------------------
__global__ void xp_l0_kernel(const float* __restrict__ x,
                             const float* __restrict__ Wx0,
                             const float* __restrict__ b0)
{
    int t = blockIdx.x;
    __shared__ float xs[BB * FF];
    __shared__ float ws[FF * GG];
    __shared__ float bs[GG];
    int tid = threadIdx.x;
    if (tid < BB * FF) {
        int b = tid / FF, d = tid % FF;
        xs[tid] = x[(size_t)b * (TT * FF) + t * FF + d];
    }
    for (int i = tid; i < FF * GG; i += 256) ws[i] = Wx0[i];
    for (int i = tid; i < GG; i += 256) bs[i] = b0[i];
    __syncthreads();
    float* dst = g_xp + (size_t)t * GG * BB;
    for (int idx = tid; idx < GG * BB; idx += 256) {
        int col = idx >> 6, b = idx & 63;
        float v = bs[col]
                + xs[b * 3 + 0] * ws[col]
                + xs[b * 3 + 1] * ws[GG + col]
                + xs[b * 3 + 2] * ws[2 * GG + col];
        dst[idx] = v;
    }
}

// ---------------- xp GEMM layers 1,2 (K=400): t-batched, f32x2 ---------------
// g_xp[t][col][b] = bias[col] + sum_u hs[t][u][b] * Wx[u][col]
// grid (25, 2, 175), block 256. CTA tile = 64 cols x 32 b x 4 t; k-chunks of 16.
// Thread: tc=tid&15 (4 cols), tbg=(tid>>4)&7 (4 b = 2 pairs), tt=tid>>7 (2 t).
// Inner iter: 1 Ws LDS.128 + 4 dup movs (shared over 4t via acc reuse... over 2t)
//             + 2 As LDS.128 + 16 FFMA2  -> FFMA2-bound with issue slack.
__global__ void __launch_bounds__(256) xp_gemm_kernel(int srcsel,
                                                      const float* __restrict__ Wx,
                                                      const float* __restrict__ bias)
{
    const float* hs = srcsel ? g_hs1 : g_hs0;
    const int c0 = blockIdx.x * 64;
    const int b0 = blockIdx.y * 32;
    const int t0 = blockIdx.z * 4;

    __shared__ float As[2][4][16][32];   // [buf][t][k][b]  8 KB/buf
    __shared__ float Ws[2][16][64];      // [buf][k][c]     4 KB/buf

    const int tid = threadIdx.x;
    const int tc  = tid & 15;
    const int tbg = (tid >> 4) & 7;
    const int tt  = tid >> 7;

    // load decomposition for As (2 float4 per thread per chunk)
    const int la_t = tid >> 7;          // with j offset below covers t 0..3
    const int la_k = (tid >> 3) & 15;
    const int la_q = tid & 7;
    // Ws: 1 float4 per thread
    const int lw_k = tid >> 4;
    const int lw_q = tid & 15;

    const float* hbase = hs + (size_t)t0 * UU * BB + b0;
    const float* wbase = Wx + c0;

    // prologue: chunk 0
    float4 pa0, pa1, pw;
    {
        pa0 = *(const float4*)(hbase + (size_t)(la_t)     * UU * BB + (size_t)la_k * BB + la_q * 4);
        pa1 = *(const float4*)(hbase + (size_t)(la_t + 2) * UU * BB + (size_t)la_k * BB + la_q * 4);
        pw  = *(const float4*)(wbase + (size_t)lw_k * GG + lw_q * 4);
        *(float4*)&As[0][la_t][la_k][la_q * 4]     = pa0;
        *(float4*)&As[0][la_t + 2][la_k][la_q * 4] = pa1;
        *(float4*)&Ws[0][lw_k][lw_q * 4]           = pw;
    }
    __syncthreads();

    ull acc[4][2][2];   // [col][bpair][tlocal]
#pragma unroll
    for (int c = 0; c < 4; c++)
#pragma unroll
        for (int p = 0; p < 2; p++) { acc[c][p][0] = 0ull; acc[c][p][1] = 0ull; }

    for (int kc = 0; kc < 25; kc++) {
        int buf = kc & 1;
        if (kc < 24) {
            size_t ko = (size_t)((kc + 1) * 16);
            pa0 = *(const float4*)(hbase + (size_t)(la_t)     * UU * BB + (ko + la_k) * BB + la_q * 4);
            pa1 = *(const float4*)(hbase + (size_t)(la_t + 2) * UU * BB + (ko + la_k) * BB + la_q * 4);
            pw  = *(const float4*)(wbase + (ko + lw_k) * GG + lw_q * 4);
        }
#pragma unroll
        for (int k = 0; k < 16; k++) {
            float4 w4 = *(const float4*)&Ws[buf][k][tc * 4];
            ull wx = dup2(w4.x), wy = dup2(w4.y), wz = dup2(w4.z), ww = dup2(w4.w);
            ulonglong2 aA = *(const ulonglong2*)&As[buf][tt * 2][k][tbg * 4];
            ulonglong2 aB = *(const ulonglong2*)&As[buf][tt * 2 + 1][k][tbg * 4];
            ffma2(acc[0][0][0], aA.x, wx); ffma2(acc[0][1][0], aA.y, wx);
            ffma2(acc[0][0][1], aB.x, wx); ffma2(acc[0][1][1], aB.y, wx);
            ffma2(acc[1][0][0], aA.x, wy); ffma2(acc[1][1][0], aA.y, wy);
            ffma2(acc[1][0][1], aB.x, wy); ffma2(acc[1][1][1], aB.y, wy);
            ffma2(acc[2][0][0], aA.x, wz); ffma2(acc[2][1][0], aA.y, wz);
            ffma2(acc[2][0][1], aB.x, wz); ffma2(acc[2][1][1], aB.y, wz);
            ffma2(acc[3][0][0], aA.x, ww); ffma2(acc[3][1][0], aA.y, ww);
            ffma2(acc[3][0][1], aB.x, ww); ffma2(acc[3][1][1], aB.y, ww);
        }
        if (kc < 24) {
            int nb = buf ^ 1;
            *(float4*)&As[nb][la_t][la_k][la_q * 4]     = pa0;
            *(float4*)&As[nb][la_t + 2][la_k][la_q * 4] = pa1;
            *(float4*)&Ws[nb][lw_k][lw_q * 4]           = pw;
            __syncthreads();
        }
    }

#pragma unroll
    for (int c = 0; c < 4; c++) {
        int col = c0 + tc * 4 + c;
        float bv = bias[col];
#pragma unroll
        for (int tl = 0; tl < 2; tl++) {
            int t = t0 + tt * 2 + tl;
            float4 o;
            o.x = f2lo(acc[c][0][tl]) + bv; o.y = f2hi(acc[c][0][tl]) + bv;
            o.z = f2lo(acc[c][1][tl]) + bv; o.w = f2hi(acc[c][1][tl]) + bv;
            *(float4*)(g_xp + ((size_t)t * GG + col) * BB + b0 + tbg * 4) = o;
        }
    }
}

// ---------------- persistent per-layer LSTM scan (R6 config, proven) ---------
// 148 CTAs x 256 threads (1/SM). CTA owns units u0..u0+2 (padded to 444).
// warp = k-slice (8 x 50 rows); colg=(tid>>3)&3 (3 cols), rowg=tid&7 (8 b).
// Warp-local refill; flag-array barrier with single-warp poll (5 lines).
#define SCAN_SMEM 178944

template<int N>
__device__ __forceinline__ void compute_rows(const float* h_sm, const ull* w2s,
                                             int k0, int rowg, int colg,
                                             ull (&acc)[3][4])
{
    const char* hp = (const char*)(h_sm + (size_t)k0 * BB + rowg * 8);
    const ull*  wp = w2s + (size_t)k0 * 16 + colg * 4;
#pragma unroll 10
    for (int it = 0; it < N; it++) {
        ulonglong2 hA = *(const ulonglong2*)hp;         // b0..b3
        ulonglong2 hB = *(const ulonglong2*)(hp + 16);  // b4..b7
        ulonglong2 wAB = *(const ulonglong2*)wp;        // cols 0,1 (pre-dup'd)
        ull wC = wp[2];                                 // col 2
        ffma2(acc[0][0], hA.x, wAB.x); ffma2(acc[0][1], hA.y, wAB.x);
        ffma2(acc[0][2], hB.x, wAB.x); ffma2(acc[0][3], hB.y, wAB.x);
        ffma2(acc[1][0], hA.x, wAB.y); ffma2(acc[1][1], hA.y, wAB.y);
        ffma2(acc[1][2], hB.x, wAB.y); ffma2(acc[1][3], hB.y, wAB.y);
        ffma2(acc[2][0], hA.x, wC);    ffma2(acc[2][1], hA.y, wC);
        ffma2(acc[2][2], hB.x, wC);    ffma2(acc[2][3], hB.y, wC);
        hp += BB * 4;
        wp += 16;
    }
}

__global__ void __launch_bounds__(256, 1) scan_kernel(const float* __restrict__ Wh_l,
                                                      const float* __restrict__ pi_l,
                                                      const float* __restrict__ pf_l,
                                                      const float* __restrict__ po_l,
                                                      int outsel)
{
    float* hs_out = outsel ? g_hs1 : g_hs0;

    extern __shared__ char smraw[];
    float* h_sm = (float*)smraw;                 // [400][64]
    ull*   w2s  = (ull*)(smraw + 102400);        // [400][16] duplicated pairs
    float* red  = (float*)(smraw + 153600);      // [8][12][64]
    float* c_sm = (float*)(smraw + 178176);      // [3][64]

    const int tid  = threadIdx.x;
    const int cta  = blockIdx.x;
    const int u0   = cta * 3;
    const int ks   = tid >> 5;          // warp id = k slice
    const int lane = tid & 31;
    const int colg = (tid >> 3) & 3;
    const int rowg = tid & 7;

    // init h_sm zero (t=0 state)
    for (int i = tid; i < UU * BB / 4; i += 256)
        ((float4*)h_sm)[i] = make_float4(0.f, 0.f, 0.f, 0.f);
    // init duplicated weights: slot s = cg*4 + j (j<3 used, j==3 pad)
    for (int i = tid; i < UU * 16; i += 256) {
        int k = i >> 4, s = i & 15;
        int cg = s >> 2, j = s & 3;
        float v = 0.f;
        if (j < 3) {
            int lc = cg * 3 + j;
            int u  = u0 + (lc >> 2);
            int g  = lc & 3;
            if (u < UU) v = Wh_l[(size_t)k * GG + g * UU + u];
        }
        w2s[i] = dup2(v);
    }
    if (tid < 3 * BB) c_sm[tid] = 0.f;

    // gate-thread constants
    float piv = 0.f, pfv = 0.f, pov = 0.f;
    int gu = 0, gb = 0, gj = 0;
    const bool gthr = (tid < 3 * BB);
    bool gvalid = false;
    if (gthr) {
        gj = tid >> 6; gb = tid & 63; gu = u0 + gj;
        gvalid = (gu < UU);
        if (gvalid) { piv = pi_l[gu]; pfv = pf_l[gu]; pov = po_l[gu]; }
    }

    unsigned base = g_flags[cta];
    __syncthreads();

    const int kbase = ks * 50;
    float4* dst4 = (float4*)(h_sm + kbase * BB);           // this warp's 50 rows
    float* rp = red + (ks * NCOL + colg * 3) * BB + rowg * 8;

    for (int t = 0; t < TT; t++) {
        // prefetch xp for the gate phase (overlaps with compute)
        float xp0 = 0.f, xp1 = 0.f, xp2 = 0.f, xp3 = 0.f;
        if (gvalid) {
            const float* xpp = g_xp + ((size_t)t * GG + gu) * BB + gb;
            xp0 = __ldg(xpp);
            xp1 = __ldg(xpp + (size_t)UU * BB);
            xp2 = __ldg(xpp + (size_t)2 * UU * BB);
            xp3 = __ldg(xpp + (size_t)3 * UU * BB);
        }

        if (t > 0) {
            // warp-local refill of own 50 h-rows: one batched LDG->STS burst
            const float4* src4 = (const float4*)(hs_out + ((size_t)(t - 1) * UU + kbase) * BB);
            float4 tmp[25];
#pragma unroll
            for (int i = 0; i < 25; i++) tmp[i] = src4[i * 32 + lane];
#pragma unroll
            for (int i = 0; i < 25; i++) dst4[i * 32 + lane] = tmp[i];
            __syncwarp();
        }

        ull acc[3][4];
#pragma unroll
        for (int c = 0; c < 3; c++)
#pragma unroll
            for (int p = 0; p < 4; p++) acc[c][p] = 0ull;

        compute_rows<50>(h_sm, w2s, kbase, rowg, colg, acc);

        // write partial sums
#pragma unroll
        for (int c = 0; c < 3; c++) {
            ulonglong2 s0; s0.x = acc[c][0]; s0.y = acc[c][1];
            ulonglong2 s1; s1.x = acc[c][2]; s1.y = acc[c][3];
            *(ulonglong2*)(rp + (size_t)c * BB)     = s0;
            *(ulonglong2*)(rp + (size_t)c * BB + 4) = s1;
        }
        __syncthreads();

        // gate phase: 192 threads, one per (unit j, batch b)
        if (gthr) {
            float s0 = 0.f, s1 = 0.f, s2 = 0.f, s3 = 0.f;
#pragma unroll
            for (int q = 0; q < 8; q++) {
                const float* r2 = red + (q * NCOL + gj * 4) * BB + gb;
                s0 += r2[0]; s1 += r2[BB]; s2 += r2[2 * BB]; s3 += r2[3 * BB];
            }
            if (gvalid) {
                float z0 = xp0 + s0, z1 = xp1 + s1, z2 = xp2 + s2, z3 = xp3 + s3;
                float cold = c_sm[tid];
                float iv = sigm(z0 + piv * cold);
                float fv = sigm(z1 + pfv * cold);
                float cn = fv * cold + iv * tanhf(z2);
                float ov = sigm(z3 + pov * cn);
                float hv = ov * tanhf(cn);
                c_sm[tid] = cn;
                hs_out[((size_t)t * UU + gu) * BB + gb] = hv;
            }
        }
        __syncthreads();   // orders gate STGs before tid0's fence

        if (t < TT - 1) {
            unsigned tgt = base + (unsigned)t + 1u;
            if (tid == 0) { __threadfence(); st_rel(&g_flags[cta], tgt); }
            if (tid < 32) {
                // single-warp poll: 5 lines, low L2 pressure
                for (;;) {
                    bool ok = true;
                    for (int i = lane; i < NCTA; i += 32)
                        if (ld_acq(&g_flags[i]) < tgt) ok = false;
                    if (__all_sync(0xffffffffu, ok)) break;
                    __nanosleep(64);
                }
            }
            __syncthreads();   // release all warps into their private refill
        }
    }
}

// ---------------- final projection ------------------------------------------
__global__ void final_kernel(const float* __restrict__ Wd,
                             const float* __restrict__ bd,
                             float* __restrict__ out)
{
    int t = blockIdx.x;
    int tid = threadIdx.x;  // 192
    __shared__ float wds[UU * FF];
    for (int i = tid; i < UU * FF; i += 192) wds[i] = Wd[i];
    __syncthreads();
    int b = tid / FF, f = tid % FF;
    const float* h = g_hs0 + (size_t)t * UU * BB;
    float acc = bd[f];
#pragma unroll 4
    for (int u = 0; u < UU; u++)
        acc += h[(size_t)u * BB + b] * wds[u * FF + f];
    out[(size_t)b * (TT * FF) + t * FF + f] = acc;
}

// ---------------- launch -----------------------------------------------------
extern "C" void kernel_launch(void* const* d_in, const int* in_sizes, int n_in,
                              void* d_out, int out_size)
{
    (void)in_sizes; (void)n_in; (void)out_size;
    const float* x   = (const float*)d_in[0];
    const float* Wx0 = (const float*)d_in[1];
    const float* Wx1 = (const float*)d_in[2];
    const float* Wx2 = (const float*)d_in[3];
    const float* Wh  = (const float*)d_in[4];
    const float* bb  = (const float*)d_in[5];
    const float* pi  = (const float*)d_in[6];
    const float* pf  = (const float*)d_in[7];
    const float* po  = (const float*)d_in[8];
    const float* Wd  = (const float*)d_in[9];
    const float* bd  = (const float*)d_in[10];
    float* out = (float*)d_out;

    cudaFuncSetAttribute(scan_kernel, cudaFuncAttributeMaxDynamicSharedMemorySize, SCAN_SMEM);

    dim3 ggrid(GG / 64, BB / 32, TT / 4);   // (25, 2, 175)

    // layer 0
    xp_l0_kernel<<<TT, 256>>>(x, Wx0, bb);
    scan_kernel<<<NCTA, 256, SCAN_SMEM>>>(Wh, pi, pf, po, /*outsel=*/0);
    // layer 1
    xp_gemm_kernel<<<ggrid, 256>>>(/*src=*/0, Wx1, bb + GG);
    scan_kernel<<<NCTA, 256, SCAN_SMEM>>>(Wh + (size_t)UU * GG, pi + UU, pf + UU, po + UU, 1);
    // layer 2
    xp_gemm_kernel<<<ggrid, 256>>>(/*src=*/1, Wx2, bb + 2 * GG);
    scan_kernel<<<NCTA, 256, SCAN_SMEM>>>(Wh + (size_t)2 * UU * GG, pi + 2 * UU, pf + 2 * UU, po + 2 * UU, 0);
    // output projection
    final_kernel<<<TT, 192>>>(Wd, bd, out);
}